// round 10
// baseline (speedup 1.0000x reference)
#include <cuda_runtime.h>

#define Bx 32
#define Tt 36
#define Nn 10000
#define Ff 3
#define Hh 10
#define Rr 20
#define NQ (Nn * Ff / 4)   // 7500 float4 per (b,t) row
#define NCHUNK 30          // 30 blocks of 256 threads cover NQ
#define NBLOCKS (NCHUNK * Bx)

// Scratch (no device allocation allowed -> __device__ globals).
// Zero-initialized at module load; the last block resets everything to zero
// after consuming it, so every graph replay starts from the same state.
__device__ float g_rsum[Bx * Rr];    // per-(b,r) regional sums   (atomics)
__device__ int   g_rcnt[Bx * Rr];    // per-(b,r) regional counts (atomics)
__device__ int   g_nanlist[4096];    // packed b*Nn+n of all-NaN nodes (exp. 0)
__device__ int   g_nancnt;           // list length
__device__ unsigned g_done;          // finished-block ticket counter

// ---------------------------------------------------------------------------
// Single fused kernel. grid = (NCHUNK, Bx), one block per (b, 1024-float
// chunk). Main loop: 36 coalesced float4 streaming loads per thread (512B per
// warp-load, __ldcs). Epilogue (fixed in R10):
//   - stage the block's ~342 channel-0 time_means into shared (divergent part
//     is now just 2 shared stores per thread, no global traffic)
//   - cooperative CONVERGENT loop: coalesced __stcs writes of out_pred
//     (NaNs written as-is; P(all-NaN node) = 0.05^36 ~ 0) and regional
//     binning via shared atomics with all lanes active
//   - flush histogram with 40 global atomics per block
// Last block (threadfence + ticket) computes regional/g1/g2, writes the 6400
// regional outputs, patches the NaN list, and re-zeroes scratch.
// cluster_id int64-vs-int32 detection per block (int64 LE in [0,20) => odd
// words all zero; false-positive prob for true int32 ~ 20^-64).
// ---------------------------------------------------------------------------
__global__ void k_main(const float4* __restrict__ seq, const int* __restrict__ cl,
                       float* __restrict__ out) {
    __shared__ float s_tmval[346];   // staged channel-0 means for this chunk
    __shared__ float s_rsum[Rr];
    __shared__ int   s_rcnt[Rr];
    __shared__ int   s_flag;
    __shared__ int   s_last;

    int tid = threadIdx.x;
    int b   = blockIdx.y;
    int cx  = blockIdx.x;
    int j   = cx * blockDim.x + tid;   // float4 column in [0, NQ)

    // Node range covered by this chunk: floats [cx*1024, cx*1024+1024)
    int fbase = cx * 1024;
    int n0    = (fbase + 2) / 3;                       // first node in chunk
    int nend  = (fbase + 1024 + 2) / 3;                // one past last
    if (nend > Nn) nend = Nn;
    int ncnt  = nend - n0;                             // 341 or 342

    if (tid < Rr) { s_rsum[tid] = 0.f; s_rcnt[tid] = 0; }
    if (tid == 0) s_flag = 1;
    __syncthreads();
    if (tid < 64) {
        bool ok = (cl[2 * tid + 1] == 0) && ((unsigned)cl[2 * tid] < (unsigned)Rr);
        if (!ok) atomicAnd(&s_flag, 0);
    }

    float s0 = 0.f, s1 = 0.f, s2 = 0.f, s3 = 0.f;
    int   c0 = 0,   c1 = 0,   c2 = 0,   c3 = 0;
    if (j < NQ) {
        const float4* p = seq + (size_t)b * Tt * NQ + j;
#pragma unroll 6
        for (int t = 0; t < Tt; t++) {
            float4 v = __ldcs(p + (size_t)t * NQ);
            bool o0 = (v.x == v.x), o1 = (v.y == v.y);
            bool o2 = (v.z == v.z), o3 = (v.w == v.w);
            s0 += o0 ? v.x : 0.f;  c0 += o0;
            s1 += o1 ? v.y : 0.f;  c1 += o1;
            s2 += o2 ? v.z : 0.f;  c2 += o2;
            s3 += o3 ? v.w : 0.f;  c3 += o3;
        }
    }

    // Stage channel-0 means into shared (cheap divergent part: <= 2 per thread)
    if (j < NQ) {
        float s[4] = {s0, s1, s2, s3};
        int   c[4] = {c0, c1, c2, c3};
        int f0 = 4 * j;
#pragma unroll
        for (int cc = 0; cc < 4; cc++) {
            int f = f0 + cc;
            if (f % 3 == 0)
                s_tmval[f / 3 - n0] = s[cc] / (float)c[cc];  // 0/0 -> NaN
        }
    }
    __syncthreads();
    int is64 = s_flag;

    // Convergent cooperative epilogue: coalesced out_pred writes + binning
    float* ob = out + (size_t)b * Hh * Nn + n0;
    for (int i = tid; i < ncnt; i += 256) {
        float tm = s_tmval[i];
        if (tm == tm) {
            int node = n0 + i;
            int id = is64 ? cl[2 * node] : cl[node];
            atomicAdd(&s_rsum[id], tm);
            atomicAdd(&s_rcnt[id], 1);
        } else {
            int slot = atomicAdd(&g_nancnt, 1);
            g_nanlist[slot & 4095] = b * Nn + (n0 + i);
        }
#pragma unroll
        for (int h = 0; h < Hh; h++)
            __stcs(ob + (size_t)h * Nn + i, tm);
    }
    __syncthreads();

    // Flush block histogram into global accumulators
    if (tid < Rr) {
        atomicAdd(&g_rsum[b * Rr + tid], s_rsum[tid]);
        atomicAdd(&g_rcnt[b * Rr + tid], s_rcnt[tid]);
    }

    // ---- last-block finalization -------------------------------------------
    __threadfence();
    if (tid == 0) {
        unsigned t = atomicAdd(&g_done, 1u);
        s_last = (t == NBLOCKS - 1);
    }
    __syncthreads();
    if (!s_last) return;

    __shared__ double s_ws[8];
    __shared__ int    s_wc[8];
    __shared__ double s_gs[8];
    __shared__ long long s_gc[8];
    __shared__ float  s_regv[Bx * Rr];
    __shared__ float  s_g1, s_g2;

    int lane = tid & 31;
    int wid  = tid >> 5;

    double gs = 0.0; long long gc = 0;
    double ls = 0.0; int lc = 0;
    for (int i = tid; i < Bx * Rr; i += blockDim.x) {
        float rs = g_rsum[i];
        int   rc = g_rcnt[i];
        float v  = rs / (float)rc;   // 0/0 -> NaN
        s_regv[i] = v;
        gs += (double)rs; gc += rc;
        if (v == v) { ls += (double)v; lc++; }
    }
#pragma unroll
    for (int o = 16; o; o >>= 1) {
        gs += __shfl_down_sync(0xffffffffu, gs, o);
        gc += __shfl_down_sync(0xffffffffu, gc, o);
        ls += __shfl_down_sync(0xffffffffu, ls, o);
        lc += __shfl_down_sync(0xffffffffu, lc, o);
    }
    if (lane == 0) { s_gs[wid] = gs; s_gc[wid] = gc; s_ws[wid] = ls; s_wc[wid] = lc; }
    __syncthreads();
    if (tid == 0) {
        double tg = 0.0; long long tgc = 0;
        double t2 = 0.0; int t2c = 0;
#pragma unroll
        for (int w = 0; w < 8; w++) {
            tg += s_gs[w]; tgc += s_gc[w];
            t2 += s_ws[w]; t2c += s_wc[w];
        }
        s_g1 = (float)(tg / (double)tgc);
        s_g2 = (float)(t2 / (double)t2c);
    }
    __syncthreads();
    float g1 = s_g1, g2 = s_g2;

    // Regional outputs: [B, H, R]
    float* oreg = out + (size_t)Bx * Hh * Nn;
    for (int i = tid; i < Bx * Hh * Rr; i += blockDim.x) {
        int bb = i / (Hh * Rr);
        int r  = i % Rr;
        float v = s_regv[bb * Rr + r];
        oreg[i] = (v == v) ? v : g2;
    }

    // Patch all-NaN nodes in out_pred with g1 (expected 0 entries)
    int cnt = g_nancnt;
    if (cnt > 4096) cnt = 4096;
    for (int i = tid; i < cnt; i += blockDim.x) {
        int packed = g_nanlist[i];
        int bb = packed / Nn;
        int n  = packed - bb * Nn;
        float* o = out + (size_t)bb * Hh * Nn + n;
#pragma unroll
        for (int h = 0; h < Hh; h++) o[(size_t)h * Nn] = g1;
    }
    __syncthreads();

    // Reset all scratch for the next graph replay
    for (int i = tid; i < Bx * Rr; i += blockDim.x) { g_rsum[i] = 0.f; g_rcnt[i] = 0; }
    if (tid == 0) { g_nancnt = 0; g_done = 0u; }
}

extern "C" void kernel_launch(void* const* d_in, const int* in_sizes, int n_in,
                              void* d_out, int out_size) {
    (void)in_sizes; (void)n_in; (void)out_size;
    const float4* seq = (const float4*)d_in[0];
    const int*    cl  = (const int*)d_in[1];
    float*        out = (float*)d_out;

    k_main<<<dim3(NCHUNK, Bx), 256>>>(seq, cl, out);
}

// round 11
// speedup vs baseline: 1.3834x; 1.3834x over previous
#include <cuda_runtime.h>

#define Bx 32
#define Tt 36
#define Nn 10000
#define Ff 3
#define Hh 10
#define Rr 20
#define NQ (Nn * Ff / 4)   // 7500 float4 per (b,t) row
#define NCHUNK 30          // 30 blocks of 256 threads cover NQ

// Scratch (no device allocation allowed -> __device__ globals).
// Zero-initialized at load; k_final re-zeroes after consuming, so every graph
// replay starts from identical state. No fences needed: the kernel boundary
// orders k_main's atomics before k_final's reads.
__device__ float g_rsum[Bx * Rr];    // per-(b,r) regional sums   (atomic)
__device__ int   g_rcnt[Bx * Rr];    // per-(b,r) regional counts (atomic)
__device__ int   g_nanlist[4096];    // packed b*Nn+n of all-NaN nodes (exp. 0)
__device__ int   g_nancnt;           // list length (reset by k_final)

// ---------------------------------------------------------------------------
// Kernel A (heavy, HBM-bound): grid = (NCHUNK, Bx). This is the R8 kernel
// (measured ~30us) with the per-block slot flush replaced by 40 fire-and-
// forget global atomicAdds (REDG). NO threadfence, NO ticket — R9 showed the
// per-block MEMBAR.GPU drain of in-flight output stores serializes block
// retirement and costs ~20us across the grid.
//  - 36 coalesced float4 loads per thread (512B per warp-load)
//  - epilogue writes time_mean straight into out_pred (NaNs as-is, patched by
//    k_final; P(all-NaN node) = 0.05^36 ~ 0) and bins into shared histogram
//  - cluster_id int64-vs-int32 detected per block (int64 LE in [0,20) => odd
//    words all zero; false-positive prob for true int32 ~ 20^-64)
// ---------------------------------------------------------------------------
__global__ void k_main(const float4* __restrict__ seq, const int* __restrict__ cl,
                       float* __restrict__ out) {
    __shared__ float s_rsum[Rr];
    __shared__ int   s_rcnt[Rr];
    __shared__ int   s_flag;

    int tid = threadIdx.x;
    int b   = blockIdx.y;
    int j   = blockIdx.x * blockDim.x + tid;   // float4 column in [0, NQ)

    if (tid < Rr) { s_rsum[tid] = 0.f; s_rcnt[tid] = 0; }
    if (tid == 0) s_flag = 1;
    __syncthreads();
    if (tid < 64) {
        bool ok = (cl[2 * tid + 1] == 0) && ((unsigned)cl[2 * tid] < (unsigned)Rr);
        if (!ok) atomicAnd(&s_flag, 0);
    }

    float s0 = 0.f, s1 = 0.f, s2 = 0.f, s3 = 0.f;
    int   c0 = 0,   c1 = 0,   c2 = 0,   c3 = 0;
    if (j < NQ) {
        const float4* p = seq + (size_t)b * Tt * NQ + j;
#pragma unroll 6
        for (int t = 0; t < Tt; t++) {
            float4 v = p[(size_t)t * NQ];
            bool o0 = (v.x == v.x), o1 = (v.y == v.y);
            bool o2 = (v.z == v.z), o3 = (v.w == v.w);
            s0 += o0 ? v.x : 0.f;  c0 += o0;
            s1 += o1 ? v.y : 0.f;  c1 += o1;
            s2 += o2 ? v.z : 0.f;  c2 += o2;
            s3 += o3 ? v.w : 0.f;  c3 += o3;
        }
    }
    __syncthreads();   // s_flag ready
    int is64 = s_flag;

    if (j < NQ) {
        float s[4] = {s0, s1, s2, s3};
        int   c[4] = {c0, c1, c2, c3};
        int f0 = 4 * j;
        float* ob = out + (size_t)b * Hh * Nn;
#pragma unroll
        for (int cc = 0; cc < 4; cc++) {
            int f = f0 + cc;
            if (f % 3 == 0) {                      // channel-0 component
                int   node = f / 3;
                float tm = s[cc] / (float)c[cc];   // 0/0 -> NaN
                float* o = ob + node;
#pragma unroll
                for (int h = 0; h < Hh; h++) o[(size_t)h * Nn] = tm;
                if (tm == tm) {
                    int id = is64 ? cl[2 * node] : cl[node];
                    atomicAdd(&s_rsum[id], tm);
                    atomicAdd(&s_rcnt[id], 1);
                } else {
                    int slot = atomicAdd(&g_nancnt, 1);
                    g_nanlist[slot & 4095] = b * Nn + node;
                }
            }
        }
    }
    __syncthreads();

    // Fire-and-forget flush (REDG, no return, no fence) and exit
    if (tid < Rr) {
        atomicAdd(&g_rsum[b * Rr + tid], s_rsum[tid]);
        atomicAdd(&g_rcnt[b * Rr + tid], s_rcnt[tid]);
    }
}

// ---------------------------------------------------------------------------
// Kernel B (single block, 640 threads, lean): reads only the 1280 accumulator
// words (vs 38400 slot loads in R8's 22us version). Computes regional[b,r],
// g1, g2; writes the 6400 regional outputs; patches NaN-list entries; resets
// all scratch for the next graph replay.
// ---------------------------------------------------------------------------
__global__ void k_final(float* __restrict__ out) {
    __shared__ double s_ws[20];
    __shared__ int    s_wc[20];
    __shared__ double s_gs[20];
    __shared__ int    s_gc[20];
    __shared__ float  s_regv[Bx * Rr];
    __shared__ float  s_g1, s_g2;

    int tid  = threadIdx.x;     // 0..639, exactly one (b,r) each
    int lane = tid & 31;
    int wid  = tid >> 5;        // 0..19

    float rs = g_rsum[tid];
    int   rc = g_rcnt[tid];
    float v  = rs / (float)rc;         // 0/0 -> NaN
    s_regv[tid] = v;

    // g1 partials (total valid-tm sum/count) and g2 partials (nanmean of regional)
    double gs = (double)rs; int gc = rc;
    double ls = (v == v) ? (double)v : 0.0;
    int    lc = (v == v) ? 1 : 0;
#pragma unroll
    for (int o = 16; o; o >>= 1) {
        gs += __shfl_down_sync(0xffffffffu, gs, o);
        gc += __shfl_down_sync(0xffffffffu, gc, o);
        ls += __shfl_down_sync(0xffffffffu, ls, o);
        lc += __shfl_down_sync(0xffffffffu, lc, o);
    }
    if (lane == 0) { s_gs[wid] = gs; s_gc[wid] = gc; s_ws[wid] = ls; s_wc[wid] = lc; }
    __syncthreads();
    if (tid == 0) {
        double tg = 0.0; long long tgc = 0;
        double t2 = 0.0; int t2c = 0;
#pragma unroll
        for (int w = 0; w < 20; w++) {
            tg += s_gs[w]; tgc += s_gc[w];
            t2 += s_ws[w]; t2c += s_wc[w];
        }
        s_g1 = (float)(tg / (double)tgc);
        s_g2 = (float)(t2 / (double)t2c);
    }
    __syncthreads();
    float g1 = s_g1, g2 = s_g2;

    // Regional outputs: [B, H, R]
    float* oreg = out + (size_t)Bx * Hh * Nn;
    for (int i = tid; i < Bx * Hh * Rr; i += blockDim.x) {
        int bb = i / (Hh * Rr);
        int r  = i % Rr;
        float vv = s_regv[bb * Rr + r];
        oreg[i] = (vv == vv) ? vv : g2;
    }

    // Patch all-NaN nodes in out_pred with g1 (expected 0 entries)
    int cnt = g_nancnt;
    if (cnt > 4096) cnt = 4096;
    for (int i = tid; i < cnt; i += blockDim.x) {
        int packed = g_nanlist[i];
        int bb = packed / Nn;
        int n  = packed - bb * Nn;
        float* o = out + (size_t)bb * Hh * Nn + n;
#pragma unroll
        for (int h = 0; h < Hh; h++) o[(size_t)h * Nn] = g1;
    }
    __syncthreads();

    // Reset scratch for the next graph replay
    g_rsum[tid] = 0.f;
    g_rcnt[tid] = 0;
    if (tid == 0) g_nancnt = 0;
}

extern "C" void kernel_launch(void* const* d_in, const int* in_sizes, int n_in,
                              void* d_out, int out_size) {
    (void)in_sizes; (void)n_in; (void)out_size;
    const float4* seq = (const float4*)d_in[0];
    const int*    cl  = (const int*)d_in[1];
    float*        out = (float*)d_out;

    k_main<<<dim3(NCHUNK, Bx), 256>>>(seq, cl, out);
    k_final<<<1, Bx * Rr>>>(out);
}